// round 14
// baseline (speedup 1.0000x reference)
#include <cuda_runtime.h>
#include <cuda_fp16.h>
#include <math.h>
#include <stdint.h>

#define N_ROWS 32768
#define DIM    256
#define KCB    8192
#define NBLK_GATHER 4096
#define GAP_THR2 2.5e-3f   // half-scale gap threshold (scores are x.e - |e|^2/2)

// ---------------------------------------------------------------------------
// scratch (device globals; no cudaMalloc allowed)
__device__ __half g_Xh[(size_t)N_ROWS * DIM];
__device__ __half g_Eh[(size_t)KCB * DIM];     // transposed: [code][dim] fp16
__device__ float  g_Et[(size_t)KCB * DIM];     // transposed: [code][dim] fp32
__device__ float g_cnorm[KCB];                 // |e|^2   (rescue, full scale)
__device__ float g_cnorm2[KCB];                // |e|^2/2 (argmax ranking)
__device__ int   g_idx[N_ROWS];
__device__ int   g_flag[N_ROWS];
__device__ int   g_hist[KCB];
__device__ float g_partials[NBLK_GATHER];
__device__ int   g_cnt;                        // flagged-row count
__device__ int   g_list[N_ROWS];               // flagged-row list
__device__ unsigned long long g_best64[N_ROWS];// packed (score,8191-k)

// ---------------------------------------------------------------------------
__device__ __forceinline__ uint32_t smem_u32(const void* p) {
    uint32_t a;
    asm("{ .reg .u64 t; cvta.to.shared.u64 t, %1; cvt.u32.u64 %0, t; }"
        : "=r"(a) : "l"(p));
    return a;
}

#define CP_ASYNC16(s, g) \
    asm volatile("cp.async.cg.shared.global [%0], [%1], 16;" :: "r"(s), "l"(g) : "memory")
#define CP_COMMIT()  asm volatile("cp.async.commit_group;" ::: "memory")
#define CP_WAIT0()   asm volatile("cp.async.wait_group 0;" ::: "memory")

__device__ __forceinline__ void ldsm4(uint32_t* r, uint32_t addr) {
    asm volatile("ldmatrix.sync.aligned.m8n8.x4.shared.b16 {%0,%1,%2,%3}, [%4];"
                 : "=r"(r[0]), "=r"(r[1]), "=r"(r[2]), "=r"(r[3]) : "r"(addr));
}

__device__ __forceinline__ void mma16816(float* c, const uint32_t* a, uint32_t b0, uint32_t b1) {
    asm volatile(
        "mma.sync.aligned.m16n8k16.row.col.f32.f16.f16.f32 "
        "{%0,%1,%2,%3}, {%4,%5,%6,%7}, {%8,%9}, {%0,%1,%2,%3};"
        : "+f"(c[0]), "+f"(c[1]), "+f"(c[2]), "+f"(c[3])
        : "r"(a[0]), "r"(a[1]), "r"(a[2]), "r"(a[3]), "r"(b0), "r"(b1));
}

// monotone float encoding for u64 max-merge; low word 8191-k (tie -> lowest k)
__device__ __forceinline__ unsigned long long pack_vk(float v, int k) {
    uint32_t b = __float_as_uint(v);
    b = (b & 0x80000000u) ? ~b : (b | 0x80000000u);
    return ((unsigned long long)b << 32) | (uint32_t)(KCB - 1 - k);
}

// smem layout: A 256 rows x 264 fp16 (stride 528B), B dbuf 128 x 136 fp16 (272B)
#define SA_BYTES 528
#define SB_BYTES 272
#define SM_A     0
#define SM_B     (256 * SA_BYTES)       // 135168
#define SB_BUF   (128 * SB_BYTES)       // 34816
#define SMEM_TOTAL (SM_B + 2 * SB_BUF)  // 204800

// ---------------------------------------------------------------------------
__global__ void splitX_kernel(const float* __restrict__ X) {
    int i = blockIdx.x * 256 + threadIdx.x;        // float4 index
    float4 x = ((const float4*)X)[i];
    __half2* p = (__half2*)(g_Xh + (size_t)i * 4);
    p[0] = __half2(__float2half(x.x), __float2half(x.y));
    p[1] = __half2(__float2half(x.z), __float2half(x.w));
}

// fused E prep: blocks [0,2048) transpose tiles; blocks [2048,2080) cnorm+zero
__global__ void __launch_bounds__(256)
prepE_kernel(const float* __restrict__ E) {
    __shared__ float t[32][33];
    const int b = blockIdx.x;
    const int tid = threadIdx.x;
    if (b < 2048) {
        int k0 = (b & 255) * 32, d0 = (b >> 8) * 32;
        int tx = tid & 31, ty = tid >> 5;              // 32 x 8
#pragma unroll
        for (int i = 0; i < 32; i += 8)
            t[ty + i][tx] = E[(size_t)(d0 + ty + i) * KCB + k0 + tx];
        __syncthreads();
#pragma unroll
        for (int i = 0; i < 32; i += 8) {
            int k = k0 + ty + i, d = d0 + tx;
            float x = t[tx][ty + i];
            g_Eh[(size_t)k * DIM + d] = __float2half(x);
            g_Et[(size_t)k * DIM + d] = x;
        }
    } else {
        int k = (b - 2048) * 256 + tid;
        g_hist[k] = 0;
        if (k == 0) g_cnt = 0;
        float s = 0.f;
#pragma unroll 8
        for (int d = 0; d < DIM; d++) {
            float e = E[d * KCB + k];
            s = fmaf(e, e, s);
        }
        g_cnorm[k]  = s;
        g_cnorm2[k] = 0.5f * s;
    }
}

// ---------------------------------------------------------------------------
// fp16 HMMA GEMM + argmax. 1024 threads, 32 warps (8m x 4n), warp tile m32 x n32.
// (frozen: measured 477 us across 3 rounds; near crossbar+tensor serialization floor)
extern __shared__ char sm_arg[];

__device__ __forceinline__ void loadB_chunk(uint32_t sb, int tid, int g, int bf) {
    int nt = g >> 1, kc = g & 1;
    const char* base = (const char*)g_Eh + (size_t)nt * 128 * 512 + kc * 256;
    uint32_t sbase = sb + SM_B + bf * SB_BUF;
#pragma unroll
    for (int i = 0; i < 2; i++) {
        int idx = tid + 1024 * i;           // 0..2047
        int c = idx >> 4, j = idx & 15;
        CP_ASYNC16(sbase + c * SB_BYTES + j * 16, base + (size_t)c * 512 + j * 16);
    }
}

__global__ void __launch_bounds__(1024, 1)
argmax_mma_kernel() {
    uint32_t sb = smem_u32(sm_arg);
    const int tid  = threadIdx.x;
    const int lane = tid & 31, wid = tid >> 5;
    const int warp_m = wid & 7, warp_n = wid >> 3;   // 8m x 4n
    const int m0 = blockIdx.x * 256;

    // A preload: 256 rows x 32 x 16B (grouped with B chunk 0)
#pragma unroll
    for (int i = 0; i < 8; i++) {
        int idx = tid + 1024 * i;           // 0..8191
        int r = idx >> 5, ch = idx & 31;
        CP_ASYNC16(sb + SM_A + r * SA_BYTES + ch * 16,
                   (const char*)g_Xh + (size_t)(m0 + r) * 512 + ch * 16);
    }
    loadB_chunk(sb, tid, 0, 0);
    CP_COMMIT();

    const uint32_t a_base = sb + SM_A
                          + (warp_m * 32 + (lane & 15)) * SA_BYTES
                          + (lane >> 4) * 16;
    const uint32_t b_addr0 = sb + SM_B
                           + (warp_n * 32 + (lane & 15)) * SB_BYTES + (lane >> 4) * 16;

    float acc[2][4][4];
#pragma unroll
    for (int mi = 0; mi < 2; mi++)
#pragma unroll
        for (int nj = 0; nj < 4; nj++)
#pragma unroll
            for (int q = 0; q < 4; q++) acc[mi][nj][q] = 0.f;

    float best[4], best2[4]; int bk[4];
#pragma unroll
    for (int s = 0; s < 4; s++) { best[s] = -3.4e38f; best2[s] = -3.4e38f; bk[s] = 0; }

    for (int g = 0; g < 128; g++) {
        int buf = g & 1;
        CP_WAIT0();
        __syncthreads();
        if (g + 1 < 128) {
            loadB_chunk(sb, tid, g + 1, buf ^ 1);
            CP_COMMIT();
        }

        const int kc = g & 1;
        const uint32_t ak = kc * 256;
        const uint32_t bb = b_addr0 + buf * SB_BUF;
#pragma unroll
        for (int kq = 0; kq < 8; kq++) {
            uint32_t bf[2][4];
#pragma unroll
            for (int jb = 0; jb < 2; jb++)
                ldsm4(bf[jb], bb + jb * (16 * SB_BYTES) + kq * 32);
#pragma unroll
            for (int mi = 0; mi < 2; mi++) {
                uint32_t af[4];
                ldsm4(af, a_base + mi * (16 * SA_BYTES) + ak + kq * 32);
                mma16816(acc[mi][0], af, bf[0][0], bf[0][2]);
                mma16816(acc[mi][1], af, bf[0][1], bf[0][3]);
                mma16816(acc[mi][2], af, bf[1][0], bf[1][2]);
                mma16816(acc[mi][3], af, bf[1][1], bf[1][3]);
            }
        }

        if (kc == 1) {                                    // tile epilogue
            const int nt = g >> 1;
            const int cb = nt * 128 + warp_n * 32 + (lane & 3) * 2;
            float cn[8];
#pragma unroll
            for (int nj = 0; nj < 4; nj++) {
                cn[nj * 2]     = __ldg(g_cnorm2 + cb + nj * 8);
                cn[nj * 2 + 1] = __ldg(g_cnorm2 + cb + nj * 8 + 1);
            }
#pragma unroll
            for (int mi = 0; mi < 2; mi++)
#pragma unroll
                for (int h = 0; h < 2; h++) {
                    const int s = mi * 2 + h;
                    float v[8];
#pragma unroll
                    for (int nj = 0; nj < 4; nj++) {
                        v[nj * 2]     = acc[mi][nj][h * 2]     - cn[nj * 2];
                        v[nj * 2 + 1] = acc[mi][nj][h * 2 + 1] - cn[nj * 2 + 1];
                    }
                    // branch-free tile max (ILP tree)
                    float m01 = fmaxf(v[0], v[1]), m23 = fmaxf(v[2], v[3]);
                    float m45 = fmaxf(v[4], v[5]), m67 = fmaxf(v[6], v[7]);
                    float m = fmaxf(fmaxf(m01, m23), fmaxf(m45, m67));
                    if (m > best[s]) {                    // rare: exact top-2 scan
                        float b1 = best[s], b2 = best2[s]; int kb = bk[s];
#pragma unroll
                        for (int nj = 0; nj < 4; nj++)
#pragma unroll
                            for (int c = 0; c < 2; c++) {
                                float vv = v[nj * 2 + c];
                                int k = cb + nj * 8 + c;
                                if (vv > b1) { b2 = b1; b1 = vv; kb = k; }
                                else if (vv > b2) b2 = vv;
                            }
                        best[s] = b1; best2[s] = b2; bk[s] = kb;
                    } else {
                        best2[s] = fmaxf(best2[s], m);
                    }
                }
#pragma unroll
            for (int mi = 0; mi < 2; mi++)
#pragma unroll
                for (int nj = 0; nj < 4; nj++)
#pragma unroll
                    for (int q = 0; q < 4; q++) acc[mi][nj][q] = 0.f;
        }
    }

    // cross-partition reduce: 16 partitions per row; scratch in A region
    __syncthreads();
    float* sB1 = (float*)(sm_arg);                 // 256*16 f32
    float* sB2 = sB1 + 4096;
    int*   sBK = (int*)(sB2 + 4096);
    const int part = warp_n * 4 + (lane & 3);
#pragma unroll
    for (int mi = 0; mi < 2; mi++)
#pragma unroll
        for (int h = 0; h < 2; h++) {
            int s = mi * 2 + h;
            int row = warp_m * 32 + mi * 16 + h * 8 + (lane >> 2);
            sB1[row * 16 + part] = best[s];
            sB2[row * 16 + part] = best2[s];
            sBK[row * 16 + part] = bk[s];
        }
    __syncthreads();
    if (tid < 256) {
        float B1 = -3.4e38f, B2 = -3.4e38f; int K1 = 0x7fffffff;
        for (int p = 0; p < 16; p++) {
            float v1 = sB1[tid * 16 + p], v2 = sB2[tid * 16 + p];
            int   k1 = sBK[tid * 16 + p];
            if (v1 > B1)       { B2 = B1; B1 = v1; K1 = k1; }
            else if (v1 == B1) { if (k1 < K1) K1 = k1; B2 = B1; }
            else if (v1 > B2)  { B2 = v1; }
            if (v2 > B2) B2 = v2;
        }
        int flag = (B1 - B2 < GAP_THR2) ? 1 : 0;
        g_idx[m0 + tid]  = K1;
        g_flag[m0 + tid] = flag;
        if (flag) {
            int p = atomicAdd(&g_cnt, 1);
            g_list[p] = m0 + tid;
            g_best64[m0 + tid] = 0ULL;
        }
    }
}

// ---------------------------------------------------------------------------
// batched exact fp32 rescore: 8 code-eighths x 64 row-slots, 16 rows/batch.
__global__ void __launch_bounds__(256)
rescue_kernel(const float* __restrict__ X, const float* __restrict__ E) {
    __shared__ float xs[16][DIM];     // 16 KB
    __shared__ int   rows_s[16];
    const int tid  = threadIdx.x;
    const int lane = tid & 31;
    const int cq = blockIdx.x & 7;    // 1024-code eighth
    const int rs = blockIdx.x >> 3;   // 0..63 row slot
    const int cnt = g_cnt;

    for (int b = rs; b * 16 < cnt; b += 64) {
        const int base = b * 16;
        const int nv = min(16, cnt - base);
        if (tid < nv) rows_s[tid] = g_list[base + tid];
        __syncthreads();
        for (int i = tid; i < nv * DIM; i += 256) {
            int r = i >> 8, d = i & 255;
            xs[r][d] = X[(size_t)rows_s[r] * DIM + d];
        }
        __syncthreads();

#pragma unroll 1
        for (int i = 0; i < 4; i++) {
            const int kk = cq * 1024 + tid + 256 * i;
            float a[16];
#pragma unroll
            for (int r = 0; r < 16; r++) a[r] = 0.f;
#pragma unroll 4
            for (int d = 0; d < DIM; d++) {
                float e = __ldg(E + (size_t)d * KCB + kk);
#pragma unroll
                for (int r = 0; r < 16; r++) a[r] = fmaf(e, xs[r][d], a[r]);
            }
            const float c = g_cnorm[kk];
#pragma unroll 1
            for (int r = 0; r < nv; r++) {
                float v = fmaf(2.f, a[r], -c);
                unsigned long long u = pack_vk(v, kk);
#pragma unroll
                for (int o = 16; o; o >>= 1) {
                    unsigned long long w = __shfl_xor_sync(0xffffffffu, u, o);
                    if (w > u) u = w;
                }
                if (lane == 0) atomicMax(&g_best64[rows_s[r]], u);
            }
        }
        __syncthreads();
    }
}

// ---------------------------------------------------------------------------
// gather for ALL rows (flagged rows decode from g_best64); coalesced via g_Et
__global__ void __launch_bounds__(256)
gather_kernel(const float* __restrict__ X,
              float* __restrict__ outq,
              float* __restrict__ outidx) {
    const int warp = threadIdx.x >> 5;
    const int lane = threadIdx.x & 31;
    const int row  = blockIdx.x * 8 + warp;
    const int k = g_flag[row]
                ? (KCB - 1 - (int)(g_best64[row] & 0xFFFFFFFFu))
                : g_idx[row];

    const float4* qv = (const float4*)(g_Et + (size_t)k * DIM);
    const float4* xv = (const float4*)(X + (size_t)row * DIM);
    float4* ov = (float4*)(outq + (size_t)row * DIM);
    float ss = 0.f;
#pragma unroll
    for (int j = 0; j < 2; j++) {
        float4 q = qv[lane + 32 * j];
        float4 x = xv[lane + 32 * j];
        ov[lane + 32 * j] = q;
        float d0 = q.x - x.x, d1 = q.y - x.y, d2 = q.z - x.z, d3 = q.w - x.w;
        ss = fmaf(d0, d0, ss); ss = fmaf(d1, d1, ss);
        ss = fmaf(d2, d2, ss); ss = fmaf(d3, d3, ss);
    }
#pragma unroll
    for (int o = 16; o; o >>= 1) ss += __shfl_xor_sync(0xffffffffu, ss, o);

    __shared__ float wss[8];
    if (lane == 0) {
        wss[warp] = ss;
        atomicAdd(&g_hist[k], 1);
        if (outidx) outidx[row] = (float)k;
    }
    __syncthreads();
    if (threadIdx.x == 0) {
        float s = 0.f;
        for (int w = 0; w < 8; w++) s += wss[w];
        g_partials[blockIdx.x] = s;
    }
}

// ---------------------------------------------------------------------------
__global__ void finalize_kernel(float* __restrict__ out_scalars) {
    __shared__ double sd[256];
    const int t = threadIdx.x;

    double s = 0.0;
    for (int i = t; i < NBLK_GATHER; i += 256) s += (double)g_partials[i];
    sd[t] = s; __syncthreads();
    for (int o = 128; o; o >>= 1) { if (t < o) sd[t] += sd[t + o]; __syncthreads(); }
    double sq = sd[0];
    __syncthreads();

    double e = 0.0;
    for (int k = t; k < KCB; k += 256) {
        float p = (float)g_hist[k] / (float)N_ROWS;
        e += (double)(p * logf(p + 1e-10f));
    }
    sd[t] = e; __syncthreads();
    for (int o = 128; o; o >>= 1) { if (t < o) sd[t] += sd[t + o]; __syncthreads(); }

    if (t == 0) {
        float mse = (float)(sq / (double)((long long)N_ROWS * DIM));
        float vq_loss = mse + 0.1f * mse;
        float entropy = -(float)sd[0];
        float usage_loss = -(entropy / logf((float)KCB));
        out_scalars[0] = vq_loss;
        out_scalars[1] = 0.1f * usage_loss;
    }
}

// ---------------------------------------------------------------------------
extern "C" void kernel_launch(void* const* d_in, const int* in_sizes, int n_in,
                              void* d_out, int out_size) {
    const float* X = (const float*)d_in[0];   // [32,32,32,256] f32
    const float* E = (const float*)d_in[1];   // [256, 8192] f32
    float* out = (float*)d_out;

    const int NQ = N_ROWS * DIM;
    float* outq   = out;
    float* outidx = (out_size >= NQ + N_ROWS)     ? out + NQ          : (float*)0;
    float* outs   = (out_size >= NQ + N_ROWS + 2) ? out + NQ + N_ROWS : (float*)0;

    cudaFuncSetAttribute(argmax_mma_kernel,
                         cudaFuncAttributeMaxDynamicSharedMemorySize, SMEM_TOTAL);

    // rescue_kernel is the 4th launch (ncu captures #4)
    splitX_kernel<<<8192, 256>>>(X);
    prepE_kernel<<<2080, 256>>>(E);
    argmax_mma_kernel<<<N_ROWS / 256, 1024, SMEM_TOTAL>>>();
    rescue_kernel<<<512, 256>>>(X, E);
    gather_kernel<<<NBLK_GATHER, 256>>>(X, outq, outidx);
    if (outs) finalize_kernel<<<1, 256>>>(outs);
}

// round 15
// speedup vs baseline: 1.0613x; 1.0613x over previous
#include <cuda_runtime.h>
#include <cuda_fp16.h>
#include <math.h>
#include <stdint.h>

#define N_ROWS 32768
#define DIM    256
#define KCB    8192
#define NBLK_GATHER 4096
#define GAP_THR2 2.5e-3f   // half-scale gap threshold (scores are x.e - |e|^2/2)

// ---------------------------------------------------------------------------
// scratch (device globals; no cudaMalloc allowed)
__device__ __half g_Xh[(size_t)N_ROWS * DIM];
__device__ __half g_Eh[(size_t)KCB * DIM];     // transposed: [code][dim] fp16
__device__ float  g_Et[(size_t)KCB * DIM];     // transposed: [code][dim] fp32
__device__ float g_cnorm[KCB];                 // |e|^2   (rescue, full scale)
__device__ float g_cnorm2[KCB];                // |e|^2/2 (argmax ranking)
__device__ int   g_idx[N_ROWS];
__device__ int   g_flag[N_ROWS];
__device__ int   g_hist[KCB];
__device__ float g_partials[NBLK_GATHER];
__device__ int   g_cnt;                        // flagged-row count
__device__ int   g_list[N_ROWS];               // flagged-row list
__device__ unsigned long long g_best64[N_ROWS];// packed (score,8191-k)

// ---------------------------------------------------------------------------
__device__ __forceinline__ uint32_t smem_u32(const void* p) {
    uint32_t a;
    asm("{ .reg .u64 t; cvta.to.shared.u64 t, %1; cvt.u32.u64 %0, t; }"
        : "=r"(a) : "l"(p));
    return a;
}

#define CP_ASYNC16(s, g) \
    asm volatile("cp.async.cg.shared.global [%0], [%1], 16;" :: "r"(s), "l"(g) : "memory")
#define CP_COMMIT()  asm volatile("cp.async.commit_group;" ::: "memory")
#define CP_WAIT0()   asm volatile("cp.async.wait_group 0;" ::: "memory")

__device__ __forceinline__ void ldsm4(uint32_t* r, uint32_t addr) {
    asm volatile("ldmatrix.sync.aligned.m8n8.x4.shared.b16 {%0,%1,%2,%3}, [%4];"
                 : "=r"(r[0]), "=r"(r[1]), "=r"(r[2]), "=r"(r[3]) : "r"(addr));
}

__device__ __forceinline__ void mma16816(float* c, const uint32_t* a, uint32_t b0, uint32_t b1) {
    asm volatile(
        "mma.sync.aligned.m16n8k16.row.col.f32.f16.f16.f32 "
        "{%0,%1,%2,%3}, {%4,%5,%6,%7}, {%8,%9}, {%0,%1,%2,%3};"
        : "+f"(c[0]), "+f"(c[1]), "+f"(c[2]), "+f"(c[3])
        : "r"(a[0]), "r"(a[1]), "r"(a[2]), "r"(a[3]), "r"(b0), "r"(b1));
}

// monotone float encoding for u64 max-merge; low word 8191-k (tie -> lowest k)
__device__ __forceinline__ unsigned long long pack_vk(float v, int k) {
    uint32_t b = __float_as_uint(v);
    b = (b & 0x80000000u) ? ~b : (b | 0x80000000u);
    return ((unsigned long long)b << 32) | (uint32_t)(KCB - 1 - k);
}

// smem layout: A 256 rows x 264 fp16 (stride 528B), B dbuf 128 x 136 fp16 (272B)
#define SA_BYTES 528
#define SB_BYTES 272
#define SM_A     0
#define SM_B     (256 * SA_BYTES)       // 135168
#define SB_BUF   (128 * SB_BYTES)       // 34816
#define SMEM_TOTAL (SM_B + 2 * SB_BUF)  // 204800

// ---------------------------------------------------------------------------
__global__ void splitX_kernel(const float* __restrict__ X) {
    int i = blockIdx.x * 256 + threadIdx.x;        // float4 index
    float4 x = ((const float4*)X)[i];
    __half2* p = (__half2*)(g_Xh + (size_t)i * 4);
    p[0] = __half2(__float2half(x.x), __float2half(x.y));
    p[1] = __half2(__float2half(x.z), __float2half(x.w));
}

// fused E prep: blocks [0,2048) transpose tiles; blocks [2048,2080) cnorm+zero
__global__ void __launch_bounds__(256)
prepE_kernel(const float* __restrict__ E) {
    __shared__ float t[32][33];
    const int b = blockIdx.x;
    const int tid = threadIdx.x;
    if (b < 2048) {
        int k0 = (b & 255) * 32, d0 = (b >> 8) * 32;
        int tx = tid & 31, ty = tid >> 5;              // 32 x 8
#pragma unroll
        for (int i = 0; i < 32; i += 8)
            t[ty + i][tx] = E[(size_t)(d0 + ty + i) * KCB + k0 + tx];
        __syncthreads();
#pragma unroll
        for (int i = 0; i < 32; i += 8) {
            int k = k0 + ty + i, d = d0 + tx;
            float x = t[tx][ty + i];
            g_Eh[(size_t)k * DIM + d] = __float2half(x);
            g_Et[(size_t)k * DIM + d] = x;
        }
    } else {
        int k = (b - 2048) * 256 + tid;
        g_hist[k] = 0;
        if (k == 0) g_cnt = 0;
        float s = 0.f;
#pragma unroll 8
        for (int d = 0; d < DIM; d++) {
            float e = E[d * KCB + k];
            s = fmaf(e, e, s);
        }
        g_cnorm[k]  = s;
        g_cnorm2[k] = 0.5f * s;
    }
}

// ---------------------------------------------------------------------------
// fp16 HMMA GEMM + argmax. 1024 threads, 32 warps (8m x 4n), warp tile m32 x n32.
// (frozen: measured ~477 us across 3 rounds; near crossbar+tensor serialization floor)
extern __shared__ char sm_arg[];

__device__ __forceinline__ void loadB_chunk(uint32_t sb, int tid, int g, int bf) {
    int nt = g >> 1, kc = g & 1;
    const char* base = (const char*)g_Eh + (size_t)nt * 128 * 512 + kc * 256;
    uint32_t sbase = sb + SM_B + bf * SB_BUF;
#pragma unroll
    for (int i = 0; i < 2; i++) {
        int idx = tid + 1024 * i;           // 0..2047
        int c = idx >> 4, j = idx & 15;
        CP_ASYNC16(sbase + c * SB_BYTES + j * 16, base + (size_t)c * 512 + j * 16);
    }
}

__global__ void __launch_bounds__(1024, 1)
argmax_mma_kernel() {
    uint32_t sb = smem_u32(sm_arg);
    const int tid  = threadIdx.x;
    const int lane = tid & 31, wid = tid >> 5;
    const int warp_m = wid & 7, warp_n = wid >> 3;   // 8m x 4n
    const int m0 = blockIdx.x * 256;

    // A preload: 256 rows x 32 x 16B (grouped with B chunk 0)
#pragma unroll
    for (int i = 0; i < 8; i++) {
        int idx = tid + 1024 * i;           // 0..8191
        int r = idx >> 5, ch = idx & 31;
        CP_ASYNC16(sb + SM_A + r * SA_BYTES + ch * 16,
                   (const char*)g_Xh + (size_t)(m0 + r) * 512 + ch * 16);
    }
    loadB_chunk(sb, tid, 0, 0);
    CP_COMMIT();

    const uint32_t a_base = sb + SM_A
                          + (warp_m * 32 + (lane & 15)) * SA_BYTES
                          + (lane >> 4) * 16;
    const uint32_t b_addr0 = sb + SM_B
                           + (warp_n * 32 + (lane & 15)) * SB_BYTES + (lane >> 4) * 16;

    float acc[2][4][4];
#pragma unroll
    for (int mi = 0; mi < 2; mi++)
#pragma unroll
        for (int nj = 0; nj < 4; nj++)
#pragma unroll
            for (int q = 0; q < 4; q++) acc[mi][nj][q] = 0.f;

    float best[4], best2[4]; int bk[4];
#pragma unroll
    for (int s = 0; s < 4; s++) { best[s] = -3.4e38f; best2[s] = -3.4e38f; bk[s] = 0; }

    for (int g = 0; g < 128; g++) {
        int buf = g & 1;
        CP_WAIT0();
        __syncthreads();
        if (g + 1 < 128) {
            loadB_chunk(sb, tid, g + 1, buf ^ 1);
            CP_COMMIT();
        }

        const int kc = g & 1;
        const uint32_t ak = kc * 256;
        const uint32_t bb = b_addr0 + buf * SB_BUF;
#pragma unroll
        for (int kq = 0; kq < 8; kq++) {
            uint32_t bf[2][4];
#pragma unroll
            for (int jb = 0; jb < 2; jb++)
                ldsm4(bf[jb], bb + jb * (16 * SB_BYTES) + kq * 32);
#pragma unroll
            for (int mi = 0; mi < 2; mi++) {
                uint32_t af[4];
                ldsm4(af, a_base + mi * (16 * SA_BYTES) + ak + kq * 32);
                mma16816(acc[mi][0], af, bf[0][0], bf[0][2]);
                mma16816(acc[mi][1], af, bf[0][1], bf[0][3]);
                mma16816(acc[mi][2], af, bf[1][0], bf[1][2]);
                mma16816(acc[mi][3], af, bf[1][1], bf[1][3]);
            }
        }

        if (kc == 1) {                                    // tile epilogue
            const int nt = g >> 1;
            const int cb = nt * 128 + warp_n * 32 + (lane & 3) * 2;
            float cn[8];
#pragma unroll
            for (int nj = 0; nj < 4; nj++) {
                cn[nj * 2]     = __ldg(g_cnorm2 + cb + nj * 8);
                cn[nj * 2 + 1] = __ldg(g_cnorm2 + cb + nj * 8 + 1);
            }
#pragma unroll
            for (int mi = 0; mi < 2; mi++)
#pragma unroll
                for (int h = 0; h < 2; h++) {
                    const int s = mi * 2 + h;
                    float v[8];
#pragma unroll
                    for (int nj = 0; nj < 4; nj++) {
                        v[nj * 2]     = acc[mi][nj][h * 2]     - cn[nj * 2];
                        v[nj * 2 + 1] = acc[mi][nj][h * 2 + 1] - cn[nj * 2 + 1];
                    }
                    // branch-free tile max (ILP tree)
                    float m01 = fmaxf(v[0], v[1]), m23 = fmaxf(v[2], v[3]);
                    float m45 = fmaxf(v[4], v[5]), m67 = fmaxf(v[6], v[7]);
                    float m = fmaxf(fmaxf(m01, m23), fmaxf(m45, m67));
                    if (m > best[s]) {                    // rare: exact top-2 scan
                        float b1 = best[s], b2 = best2[s]; int kb = bk[s];
#pragma unroll
                        for (int nj = 0; nj < 4; nj++)
#pragma unroll
                            for (int c = 0; c < 2; c++) {
                                float vv = v[nj * 2 + c];
                                int k = cb + nj * 8 + c;
                                if (vv > b1) { b2 = b1; b1 = vv; kb = k; }
                                else if (vv > b2) b2 = vv;
                            }
                        best[s] = b1; best2[s] = b2; bk[s] = kb;
                    } else {
                        best2[s] = fmaxf(best2[s], m);
                    }
                }
#pragma unroll
            for (int mi = 0; mi < 2; mi++)
#pragma unroll
                for (int nj = 0; nj < 4; nj++)
#pragma unroll
                    for (int q = 0; q < 4; q++) acc[mi][nj][q] = 0.f;
        }
    }

    // cross-partition reduce: 16 partitions per row; scratch in A region
    __syncthreads();
    float* sB1 = (float*)(sm_arg);                 // 256*16 f32
    float* sB2 = sB1 + 4096;
    int*   sBK = (int*)(sB2 + 4096);
    const int part = warp_n * 4 + (lane & 3);
#pragma unroll
    for (int mi = 0; mi < 2; mi++)
#pragma unroll
        for (int h = 0; h < 2; h++) {
            int s = mi * 2 + h;
            int row = warp_m * 32 + mi * 16 + h * 8 + (lane >> 2);
            sB1[row * 16 + part] = best[s];
            sB2[row * 16 + part] = best2[s];
            sBK[row * 16 + part] = bk[s];
        }
    __syncthreads();
    if (tid < 256) {
        float B1 = -3.4e38f, B2 = -3.4e38f; int K1 = 0x7fffffff;
        for (int p = 0; p < 16; p++) {
            float v1 = sB1[tid * 16 + p], v2 = sB2[tid * 16 + p];
            int   k1 = sBK[tid * 16 + p];
            if (v1 > B1)       { B2 = B1; B1 = v1; K1 = k1; }
            else if (v1 == B1) { if (k1 < K1) K1 = k1; B2 = B1; }
            else if (v1 > B2)  { B2 = v1; }
            if (v2 > B2) B2 = v2;
        }
        int flag = (B1 - B2 < GAP_THR2) ? 1 : 0;
        g_idx[m0 + tid]  = K1;
        g_flag[m0 + tid] = flag;
        if (flag) {
            int p = atomicAdd(&g_cnt, 1);
            g_list[p] = m0 + tid;
            g_best64[m0 + tid] = 0ULL;
        }
    }
}

// ---------------------------------------------------------------------------
// batched exact fp32 rescore, grid-stride over work items:
// item = (batch of 8 rows) x (code slice of 256). Persistent 1184 blocks.
__global__ void __launch_bounds__(256)
rescue_kernel(const float* __restrict__ X, const float* __restrict__ E) {
    __shared__ float xs[8][DIM];      // 8 KB
    __shared__ int   rows_s[8];
    const int tid  = threadIdx.x;
    const int lane = tid & 31;
    const int cnt = g_cnt;
    const int nb = (cnt + 7) >> 3;            // batches of 8 rows
    const int nitems = nb << 5;               // x 32 code slices

    int cur_b = -1;
    for (int w = blockIdx.x; w < nitems; w += gridDim.x) {
        const int b = w >> 5;
        const int slice = w & 31;
        const int base = b * 8;
        const int nv = min(8, cnt - base);

        if (b != cur_b) {                     // (re)load row batch into smem
            __syncthreads();                  // prior reads of xs done
            if (tid < nv) rows_s[tid] = g_list[base + tid];
            __syncthreads();
            for (int i = tid; i < nv * DIM; i += 256) {
                int r = i >> 8, d = i & 255;
                xs[r][d] = X[(size_t)rows_s[r] * DIM + d];
            }
            __syncthreads();
            cur_b = b;
        }

        const int kk = slice * 256 + tid;     // one code per thread
        float a0 = 0.f, a1 = 0.f, a2 = 0.f, a3 = 0.f;
        float a4 = 0.f, a5 = 0.f, a6 = 0.f, a7 = 0.f;
#pragma unroll 8
        for (int d = 0; d < DIM; d++) {
            float e = __ldg(E + (size_t)d * KCB + kk);
            a0 = fmaf(e, xs[0][d], a0);
            a1 = fmaf(e, xs[1][d], a1);
            a2 = fmaf(e, xs[2][d], a2);
            a3 = fmaf(e, xs[3][d], a3);
            a4 = fmaf(e, xs[4][d], a4);
            a5 = fmaf(e, xs[5][d], a5);
            a6 = fmaf(e, xs[6][d], a6);
            a7 = fmaf(e, xs[7][d], a7);
        }
        const float c = g_cnorm[kk];
        float accs[8] = {a0, a1, a2, a3, a4, a5, a6, a7};
#pragma unroll 1
        for (int r = 0; r < nv; r++) {
            float v = fmaf(2.f, accs[r], -c);
            unsigned long long u = pack_vk(v, kk);
#pragma unroll
            for (int o = 16; o; o >>= 1) {
                unsigned long long ww = __shfl_xor_sync(0xffffffffu, u, o);
                if (ww > u) u = ww;
            }
            if (lane == 0) atomicMax(&g_best64[rows_s[r]], u);
        }
    }
}

// ---------------------------------------------------------------------------
// gather for ALL rows (flagged rows decode from g_best64); coalesced via g_Et
__global__ void __launch_bounds__(256)
gather_kernel(const float* __restrict__ X,
              float* __restrict__ outq,
              float* __restrict__ outidx) {
    const int warp = threadIdx.x >> 5;
    const int lane = threadIdx.x & 31;
    const int row  = blockIdx.x * 8 + warp;
    const int k = g_flag[row]
                ? (KCB - 1 - (int)(g_best64[row] & 0xFFFFFFFFu))
                : g_idx[row];

    const float4* qv = (const float4*)(g_Et + (size_t)k * DIM);
    const float4* xv = (const float4*)(X + (size_t)row * DIM);
    float4* ov = (float4*)(outq + (size_t)row * DIM);
    float ss = 0.f;
#pragma unroll
    for (int j = 0; j < 2; j++) {
        float4 q = qv[lane + 32 * j];
        float4 x = xv[lane + 32 * j];
        ov[lane + 32 * j] = q;
        float d0 = q.x - x.x, d1 = q.y - x.y, d2 = q.z - x.z, d3 = q.w - x.w;
        ss = fmaf(d0, d0, ss); ss = fmaf(d1, d1, ss);
        ss = fmaf(d2, d2, ss); ss = fmaf(d3, d3, ss);
    }
#pragma unroll
    for (int o = 16; o; o >>= 1) ss += __shfl_xor_sync(0xffffffffu, ss, o);

    __shared__ float wss[8];
    if (lane == 0) {
        wss[warp] = ss;
        atomicAdd(&g_hist[k], 1);
        if (outidx) outidx[row] = (float)k;
    }
    __syncthreads();
    if (threadIdx.x == 0) {
        float s = 0.f;
        for (int w = 0; w < 8; w++) s += wss[w];
        g_partials[blockIdx.x] = s;
    }
}

// ---------------------------------------------------------------------------
__global__ void finalize_kernel(float* __restrict__ out_scalars) {
    __shared__ double sd[256];
    const int t = threadIdx.x;

    double s = 0.0;
    for (int i = t; i < NBLK_GATHER; i += 256) s += (double)g_partials[i];
    sd[t] = s; __syncthreads();
    for (int o = 128; o; o >>= 1) { if (t < o) sd[t] += sd[t + o]; __syncthreads(); }
    double sq = sd[0];
    __syncthreads();

    double e = 0.0;
    for (int k = t; k < KCB; k += 256) {
        float p = (float)g_hist[k] / (float)N_ROWS;
        e += (double)(p * logf(p + 1e-10f));
    }
    sd[t] = e; __syncthreads();
    for (int o = 128; o; o >>= 1) { if (t < o) sd[t] += sd[t + o]; __syncthreads(); }

    if (t == 0) {
        float mse = (float)(sq / (double)((long long)N_ROWS * DIM));
        float vq_loss = mse + 0.1f * mse;
        float entropy = -(float)sd[0];
        float usage_loss = -(entropy / logf((float)KCB));
        out_scalars[0] = vq_loss;
        out_scalars[1] = 0.1f * usage_loss;
    }
}

// ---------------------------------------------------------------------------
extern "C" void kernel_launch(void* const* d_in, const int* in_sizes, int n_in,
                              void* d_out, int out_size) {
    const float* X = (const float*)d_in[0];   // [32,32,32,256] f32
    const float* E = (const float*)d_in[1];   // [256, 8192] f32
    float* out = (float*)d_out;

    const int NQ = N_ROWS * DIM;
    float* outq   = out;
    float* outidx = (out_size >= NQ + N_ROWS)     ? out + NQ          : (float*)0;
    float* outs   = (out_size >= NQ + N_ROWS + 2) ? out + NQ + N_ROWS : (float*)0;

    cudaFuncSetAttribute(argmax_mma_kernel,
                         cudaFuncAttributeMaxDynamicSharedMemorySize, SMEM_TOTAL);

    // rescue_kernel is the 4th launch (ncu captures #4)
    splitX_kernel<<<8192, 256>>>(X);
    prepE_kernel<<<2080, 256>>>(E);
    argmax_mma_kernel<<<N_ROWS / 256, 1024, SMEM_TOTAL>>>();
    rescue_kernel<<<1184, 256>>>(X, E);
    gather_kernel<<<NBLK_GATHER, 256>>>(X, outq, outidx);
    if (outs) finalize_kernel<<<1, 256>>>(outs);
}

// round 16
// speedup vs baseline: 1.0718x; 1.0099x over previous
#include <cuda_runtime.h>
#include <cuda_fp16.h>
#include <math.h>
#include <stdint.h>

#define N_ROWS 32768
#define DIM    256
#define KCB    8192
#define NBLK_GATHER 4096
#define GAP_THR2 2.5e-3f   // half-scale gap threshold (scores are x.e - |e|^2/2)

// ---------------------------------------------------------------------------
// scratch (device globals; no cudaMalloc allowed)
__device__ __half g_Xh[(size_t)N_ROWS * DIM];
__device__ __half g_Eh[(size_t)KCB * DIM];     // transposed: [code][dim] fp16
__device__ float  g_Et[(size_t)KCB * DIM];     // transposed: [code][dim] fp32
__device__ float g_cnorm[KCB];                 // |e|^2   (rescue, full scale)
__device__ float g_cnorm2[KCB];                // |e|^2/2 (argmax ranking)
__device__ int   g_idx[N_ROWS];
__device__ int   g_flag[N_ROWS];
__device__ int   g_hist[KCB];
__device__ float g_partials[NBLK_GATHER];
__device__ int   g_cnt;                        // flagged-row count
__device__ int   g_list[N_ROWS];               // flagged-row list
__device__ unsigned long long g_best64[N_ROWS];// packed (score,8191-k)

// ---------------------------------------------------------------------------
__device__ __forceinline__ uint32_t smem_u32(const void* p) {
    uint32_t a;
    asm("{ .reg .u64 t; cvta.to.shared.u64 t, %1; cvt.u32.u64 %0, t; }"
        : "=r"(a) : "l"(p));
    return a;
}

#define CP_ASYNC16(s, g) \
    asm volatile("cp.async.cg.shared.global [%0], [%1], 16;" :: "r"(s), "l"(g) : "memory")
#define CP_COMMIT()  asm volatile("cp.async.commit_group;" ::: "memory")
#define CP_WAIT0()   asm volatile("cp.async.wait_group 0;" ::: "memory")

__device__ __forceinline__ void ldsm4(uint32_t* r, uint32_t addr) {
    asm volatile("ldmatrix.sync.aligned.m8n8.x4.shared.b16 {%0,%1,%2,%3}, [%4];"
                 : "=r"(r[0]), "=r"(r[1]), "=r"(r[2]), "=r"(r[3]) : "r"(addr));
}

__device__ __forceinline__ void mma16816(float* c, const uint32_t* a, uint32_t b0, uint32_t b1) {
    asm volatile(
        "mma.sync.aligned.m16n8k16.row.col.f32.f16.f16.f32 "
        "{%0,%1,%2,%3}, {%4,%5,%6,%7}, {%8,%9}, {%0,%1,%2,%3};"
        : "+f"(c[0]), "+f"(c[1]), "+f"(c[2]), "+f"(c[3])
        : "r"(a[0]), "r"(a[1]), "r"(a[2]), "r"(a[3]), "r"(b0), "r"(b1));
}

// monotone float encoding for u64 max-merge; low word 8191-k (tie -> lowest k)
__device__ __forceinline__ unsigned long long pack_vk(float v, int k) {
    uint32_t b = __float_as_uint(v);
    b = (b & 0x80000000u) ? ~b : (b | 0x80000000u);
    return ((unsigned long long)b << 32) | (uint32_t)(KCB - 1 - k);
}

// smem layout: A 256 rows x 264 fp16 (stride 528B), B dbuf 128 x 136 fp16 (272B)
#define SA_BYTES 528
#define SB_BYTES 272
#define SM_A     0
#define SM_B     (256 * SA_BYTES)       // 135168
#define SB_BUF   (128 * SB_BYTES)       // 34816
#define SMEM_TOTAL (SM_B + 2 * SB_BUF)  // 204800

// ---------------------------------------------------------------------------
__global__ void splitX_kernel(const float* __restrict__ X) {
    int i = blockIdx.x * 256 + threadIdx.x;        // float4 index
    float4 x = ((const float4*)X)[i];
    __half2* p = (__half2*)(g_Xh + (size_t)i * 4);
    p[0] = __half2(__float2half(x.x), __float2half(x.y));
    p[1] = __half2(__float2half(x.z), __float2half(x.w));
}

// fused E prep: blocks [0,2048) transpose tiles; blocks [2048,2080) cnorm+zero
__global__ void __launch_bounds__(256)
prepE_kernel(const float* __restrict__ E) {
    __shared__ float t[32][33];
    const int b = blockIdx.x;
    const int tid = threadIdx.x;
    if (b < 2048) {
        int k0 = (b & 255) * 32, d0 = (b >> 8) * 32;
        int tx = tid & 31, ty = tid >> 5;              // 32 x 8
#pragma unroll
        for (int i = 0; i < 32; i += 8)
            t[ty + i][tx] = E[(size_t)(d0 + ty + i) * KCB + k0 + tx];
        __syncthreads();
#pragma unroll
        for (int i = 0; i < 32; i += 8) {
            int k = k0 + ty + i, d = d0 + tx;
            float x = t[tx][ty + i];
            g_Eh[(size_t)k * DIM + d] = __float2half(x);
            g_Et[(size_t)k * DIM + d] = x;
        }
    } else {
        int k = (b - 2048) * 256 + tid;
        g_hist[k] = 0;
        if (k == 0) g_cnt = 0;
        float s = 0.f;
#pragma unroll 8
        for (int d = 0; d < DIM; d++) {
            float e = E[d * KCB + k];
            s = fmaf(e, e, s);
        }
        g_cnorm[k]  = s;
        g_cnorm2[k] = 0.5f * s;
    }
}

// ---------------------------------------------------------------------------
// fp16 HMMA GEMM + argmax. 1024 threads, 32 warps (8m x 4n), warp tile m32 x n32.
// (frozen: measured ~477 us across 3 rounds; near crossbar+tensor serialization floor)
extern __shared__ char sm_arg[];

__device__ __forceinline__ void loadB_chunk(uint32_t sb, int tid, int g, int bf) {
    int nt = g >> 1, kc = g & 1;
    const char* base = (const char*)g_Eh + (size_t)nt * 128 * 512 + kc * 256;
    uint32_t sbase = sb + SM_B + bf * SB_BUF;
#pragma unroll
    for (int i = 0; i < 2; i++) {
        int idx = tid + 1024 * i;           // 0..2047
        int c = idx >> 4, j = idx & 15;
        CP_ASYNC16(sbase + c * SB_BYTES + j * 16, base + (size_t)c * 512 + j * 16);
    }
}

__global__ void __launch_bounds__(1024, 1)
argmax_mma_kernel() {
    uint32_t sb = smem_u32(sm_arg);
    const int tid  = threadIdx.x;
    const int lane = tid & 31, wid = tid >> 5;
    const int warp_m = wid & 7, warp_n = wid >> 3;   // 8m x 4n
    const int m0 = blockIdx.x * 256;

    // A preload: 256 rows x 32 x 16B (grouped with B chunk 0)
#pragma unroll
    for (int i = 0; i < 8; i++) {
        int idx = tid + 1024 * i;           // 0..8191
        int r = idx >> 5, ch = idx & 31;
        CP_ASYNC16(sb + SM_A + r * SA_BYTES + ch * 16,
                   (const char*)g_Xh + (size_t)(m0 + r) * 512 + ch * 16);
    }
    loadB_chunk(sb, tid, 0, 0);
    CP_COMMIT();

    const uint32_t a_base = sb + SM_A
                          + (warp_m * 32 + (lane & 15)) * SA_BYTES
                          + (lane >> 4) * 16;
    const uint32_t b_addr0 = sb + SM_B
                           + (warp_n * 32 + (lane & 15)) * SB_BYTES + (lane >> 4) * 16;

    float acc[2][4][4];
#pragma unroll
    for (int mi = 0; mi < 2; mi++)
#pragma unroll
        for (int nj = 0; nj < 4; nj++)
#pragma unroll
            for (int q = 0; q < 4; q++) acc[mi][nj][q] = 0.f;

    float best[4], best2[4]; int bk[4];
#pragma unroll
    for (int s = 0; s < 4; s++) { best[s] = -3.4e38f; best2[s] = -3.4e38f; bk[s] = 0; }

    for (int g = 0; g < 128; g++) {
        int buf = g & 1;
        CP_WAIT0();
        __syncthreads();
        if (g + 1 < 128) {
            loadB_chunk(sb, tid, g + 1, buf ^ 1);
            CP_COMMIT();
        }

        const int kc = g & 1;
        const uint32_t ak = kc * 256;
        const uint32_t bb = b_addr0 + buf * SB_BUF;
#pragma unroll
        for (int kq = 0; kq < 8; kq++) {
            uint32_t bf[2][4];
#pragma unroll
            for (int jb = 0; jb < 2; jb++)
                ldsm4(bf[jb], bb + jb * (16 * SB_BYTES) + kq * 32);
#pragma unroll
            for (int mi = 0; mi < 2; mi++) {
                uint32_t af[4];
                ldsm4(af, a_base + mi * (16 * SA_BYTES) + ak + kq * 32);
                mma16816(acc[mi][0], af, bf[0][0], bf[0][2]);
                mma16816(acc[mi][1], af, bf[0][1], bf[0][3]);
                mma16816(acc[mi][2], af, bf[1][0], bf[1][2]);
                mma16816(acc[mi][3], af, bf[1][1], bf[1][3]);
            }
        }

        if (kc == 1) {                                    // tile epilogue
            const int nt = g >> 1;
            const int cb = nt * 128 + warp_n * 32 + (lane & 3) * 2;
            float cn[8];
#pragma unroll
            for (int nj = 0; nj < 4; nj++) {
                cn[nj * 2]     = __ldg(g_cnorm2 + cb + nj * 8);
                cn[nj * 2 + 1] = __ldg(g_cnorm2 + cb + nj * 8 + 1);
            }
#pragma unroll
            for (int mi = 0; mi < 2; mi++)
#pragma unroll
                for (int h = 0; h < 2; h++) {
                    const int s = mi * 2 + h;
                    float v[8];
#pragma unroll
                    for (int nj = 0; nj < 4; nj++) {
                        v[nj * 2]     = acc[mi][nj][h * 2]     - cn[nj * 2];
                        v[nj * 2 + 1] = acc[mi][nj][h * 2 + 1] - cn[nj * 2 + 1];
                    }
                    // branch-free tile max (ILP tree)
                    float m01 = fmaxf(v[0], v[1]), m23 = fmaxf(v[2], v[3]);
                    float m45 = fmaxf(v[4], v[5]), m67 = fmaxf(v[6], v[7]);
                    float m = fmaxf(fmaxf(m01, m23), fmaxf(m45, m67));
                    if (m > best[s]) {                    // rare: exact top-2 scan
                        float b1 = best[s], b2 = best2[s]; int kb = bk[s];
#pragma unroll
                        for (int nj = 0; nj < 4; nj++)
#pragma unroll
                            for (int c = 0; c < 2; c++) {
                                float vv = v[nj * 2 + c];
                                int k = cb + nj * 8 + c;
                                if (vv > b1) { b2 = b1; b1 = vv; kb = k; }
                                else if (vv > b2) b2 = vv;
                            }
                        best[s] = b1; best2[s] = b2; bk[s] = kb;
                    } else {
                        best2[s] = fmaxf(best2[s], m);
                    }
                }
#pragma unroll
            for (int mi = 0; mi < 2; mi++)
#pragma unroll
                for (int nj = 0; nj < 4; nj++)
#pragma unroll
                    for (int q = 0; q < 4; q++) acc[mi][nj][q] = 0.f;
        }
    }

    // cross-partition reduce: 16 partitions per row; scratch in A region
    __syncthreads();
    float* sB1 = (float*)(sm_arg);                 // 256*16 f32
    float* sB2 = sB1 + 4096;
    int*   sBK = (int*)(sB2 + 4096);
    const int part = warp_n * 4 + (lane & 3);
#pragma unroll
    for (int mi = 0; mi < 2; mi++)
#pragma unroll
        for (int h = 0; h < 2; h++) {
            int s = mi * 2 + h;
            int row = warp_m * 32 + mi * 16 + h * 8 + (lane >> 2);
            sB1[row * 16 + part] = best[s];
            sB2[row * 16 + part] = best2[s];
            sBK[row * 16 + part] = bk[s];
        }
    __syncthreads();
    if (tid < 256) {
        float B1 = -3.4e38f, B2 = -3.4e38f; int K1 = 0x7fffffff;
        for (int p = 0; p < 16; p++) {
            float v1 = sB1[tid * 16 + p], v2 = sB2[tid * 16 + p];
            int   k1 = sBK[tid * 16 + p];
            if (v1 > B1)       { B2 = B1; B1 = v1; K1 = k1; }
            else if (v1 == B1) { if (k1 < K1) K1 = k1; B2 = B1; }
            else if (v1 > B2)  { B2 = v1; }
            if (v2 > B2) B2 = v2;
        }
        int flag = (B1 - B2 < GAP_THR2) ? 1 : 0;
        g_idx[m0 + tid]  = K1;
        g_flag[m0 + tid] = flag;
        if (flag) {
            int p = atomicAdd(&g_cnt, 1);
            g_list[p] = m0 + tid;
            g_best64[m0 + tid] = 0ULL;
        }
    }
}

// ---------------------------------------------------------------------------
// batched exact fp32 rescore, grid-stride over work items:
// item = (batch of 8 rows) x (code slice of 256). Vectorized xs via LDS.128.
__global__ void __launch_bounds__(256)
rescue_kernel(const float* __restrict__ X, const float* __restrict__ E) {
    __shared__ float xs[8][DIM];      // 8 KB, rows 1KB-aligned (float4 safe)
    __shared__ int   rows_s[8];
    const int tid  = threadIdx.x;
    const int lane = tid & 31;
    const int cnt = g_cnt;
    const int nb = (cnt + 7) >> 3;            // batches of 8 rows
    const int nitems = nb << 5;               // x 32 code slices

    int cur_b = -1;
    for (int w = blockIdx.x; w < nitems; w += gridDim.x) {
        const int b = w >> 5;
        const int slice = w & 31;
        const int base = b * 8;
        const int nv = min(8, cnt - base);

        if (b != cur_b) {                     // (re)load row batch into smem
            __syncthreads();                  // prior reads of xs done
            if (tid < nv) rows_s[tid] = g_list[base + tid];
            __syncthreads();
            for (int i = tid; i < nv * DIM; i += 256) {
                int r = i >> 8, d = i & 255;
                xs[r][d] = X[(size_t)rows_s[r] * DIM + d];
            }
            __syncthreads();
            cur_b = b;
        }

        const int kk = slice * 256 + tid;     // one code per thread
        float a0 = 0.f, a1 = 0.f, a2 = 0.f, a3 = 0.f;
        float a4 = 0.f, a5 = 0.f, a6 = 0.f, a7 = 0.f;
#pragma unroll 4
        for (int d = 0; d < DIM; d += 4) {    // 4 E vals + float4 xs per row
            const float* ep = E + (size_t)d * KCB + kk;
            float e0 = __ldg(ep);
            float e1 = __ldg(ep + KCB);
            float e2 = __ldg(ep + 2 * KCB);
            float e3 = __ldg(ep + 3 * KCB);
            float4 x0 = *(const float4*)&xs[0][d];
            float4 x1 = *(const float4*)&xs[1][d];
            float4 x2 = *(const float4*)&xs[2][d];
            float4 x3 = *(const float4*)&xs[3][d];
            a0 = fmaf(e0, x0.x, a0); a0 = fmaf(e1, x0.y, a0);
            a0 = fmaf(e2, x0.z, a0); a0 = fmaf(e3, x0.w, a0);
            a1 = fmaf(e0, x1.x, a1); a1 = fmaf(e1, x1.y, a1);
            a1 = fmaf(e2, x1.z, a1); a1 = fmaf(e3, x1.w, a1);
            a2 = fmaf(e0, x2.x, a2); a2 = fmaf(e1, x2.y, a2);
            a2 = fmaf(e2, x2.z, a2); a2 = fmaf(e3, x2.w, a2);
            a3 = fmaf(e0, x3.x, a3); a3 = fmaf(e1, x3.y, a3);
            a3 = fmaf(e2, x3.z, a3); a3 = fmaf(e3, x3.w, a3);
            float4 x4 = *(const float4*)&xs[4][d];
            float4 x5 = *(const float4*)&xs[5][d];
            float4 x6 = *(const float4*)&xs[6][d];
            float4 x7 = *(const float4*)&xs[7][d];
            a4 = fmaf(e0, x4.x, a4); a4 = fmaf(e1, x4.y, a4);
            a4 = fmaf(e2, x4.z, a4); a4 = fmaf(e3, x4.w, a4);
            a5 = fmaf(e0, x5.x, a5); a5 = fmaf(e1, x5.y, a5);
            a5 = fmaf(e2, x5.z, a5); a5 = fmaf(e3, x5.w, a5);
            a6 = fmaf(e0, x6.x, a6); a6 = fmaf(e1, x6.y, a6);
            a6 = fmaf(e2, x6.z, a6); a6 = fmaf(e3, x6.w, a6);
            a7 = fmaf(e0, x7.x, a7); a7 = fmaf(e1, x7.y, a7);
            a7 = fmaf(e2, x7.z, a7); a7 = fmaf(e3, x7.w, a7);
        }
        const float c = g_cnorm[kk];
        float accs[8] = {a0, a1, a2, a3, a4, a5, a6, a7};
#pragma unroll 1
        for (int r = 0; r < nv; r++) {
            float v = fmaf(2.f, accs[r], -c);
            unsigned long long u = pack_vk(v, kk);
#pragma unroll
            for (int o = 16; o; o >>= 1) {
                unsigned long long ww = __shfl_xor_sync(0xffffffffu, u, o);
                if (ww > u) u = ww;
            }
            if (lane == 0) atomicMax(&g_best64[rows_s[r]], u);
        }
    }
}

// ---------------------------------------------------------------------------
// gather for ALL rows (flagged rows decode from g_best64); coalesced via g_Et
__global__ void __launch_bounds__(256)
gather_kernel(const float* __restrict__ X,
              float* __restrict__ outq,
              float* __restrict__ outidx) {
    const int warp = threadIdx.x >> 5;
    const int lane = threadIdx.x & 31;
    const int row  = blockIdx.x * 8 + warp;
    const int k = g_flag[row]
                ? (KCB - 1 - (int)(g_best64[row] & 0xFFFFFFFFu))
                : g_idx[row];

    const float4* qv = (const float4*)(g_Et + (size_t)k * DIM);
    const float4* xv = (const float4*)(X + (size_t)row * DIM);
    float4* ov = (float4*)(outq + (size_t)row * DIM);
    float ss = 0.f;
#pragma unroll
    for (int j = 0; j < 2; j++) {
        float4 q = qv[lane + 32 * j];
        float4 x = xv[lane + 32 * j];
        ov[lane + 32 * j] = q;
        float d0 = q.x - x.x, d1 = q.y - x.y, d2 = q.z - x.z, d3 = q.w - x.w;
        ss = fmaf(d0, d0, ss); ss = fmaf(d1, d1, ss);
        ss = fmaf(d2, d2, ss); ss = fmaf(d3, d3, ss);
    }
#pragma unroll
    for (int o = 16; o; o >>= 1) ss += __shfl_xor_sync(0xffffffffu, ss, o);

    __shared__ float wss[8];
    if (lane == 0) {
        wss[warp] = ss;
        atomicAdd(&g_hist[k], 1);
        if (outidx) outidx[row] = (float)k;
    }
    __syncthreads();
    if (threadIdx.x == 0) {
        float s = 0.f;
        for (int w = 0; w < 8; w++) s += wss[w];
        g_partials[blockIdx.x] = s;
    }
}

// ---------------------------------------------------------------------------
__global__ void finalize_kernel(float* __restrict__ out_scalars) {
    __shared__ double sd[256];
    const int t = threadIdx.x;

    double s = 0.0;
    for (int i = t; i < NBLK_GATHER; i += 256) s += (double)g_partials[i];
    sd[t] = s; __syncthreads();
    for (int o = 128; o; o >>= 1) { if (t < o) sd[t] += sd[t + o]; __syncthreads(); }
    double sq = sd[0];
    __syncthreads();

    double e = 0.0;
    for (int k = t; k < KCB; k += 256) {
        float p = (float)g_hist[k] / (float)N_ROWS;
        e += (double)(p * logf(p + 1e-10f));
    }
    sd[t] = e; __syncthreads();
    for (int o = 128; o; o >>= 1) { if (t < o) sd[t] += sd[t + o]; __syncthreads(); }

    if (t == 0) {
        float mse = (float)(sq / (double)((long long)N_ROWS * DIM));
        float vq_loss = mse + 0.1f * mse;
        float entropy = -(float)sd[0];
        float usage_loss = -(entropy / logf((float)KCB));
        out_scalars[0] = vq_loss;
        out_scalars[1] = 0.1f * usage_loss;
    }
}

// ---------------------------------------------------------------------------
extern "C" void kernel_launch(void* const* d_in, const int* in_sizes, int n_in,
                              void* d_out, int out_size) {
    const float* X = (const float*)d_in[0];   // [32,32,32,256] f32
    const float* E = (const float*)d_in[1];   // [256, 8192] f32
    float* out = (float*)d_out;

    const int NQ = N_ROWS * DIM;
    float* outq   = out;
    float* outidx = (out_size >= NQ + N_ROWS)     ? out + NQ          : (float*)0;
    float* outs   = (out_size >= NQ + N_ROWS + 2) ? out + NQ + N_ROWS : (float*)0;

    cudaFuncSetAttribute(argmax_mma_kernel,
                         cudaFuncAttributeMaxDynamicSharedMemorySize, SMEM_TOTAL);

    // rescue_kernel is the 4th launch (ncu captures #4)
    splitX_kernel<<<8192, 256>>>(X);
    prepE_kernel<<<2080, 256>>>(E);
    argmax_mma_kernel<<<N_ROWS / 256, 1024, SMEM_TOTAL>>>();
    rescue_kernel<<<1184, 256>>>(X, E);
    gather_kernel<<<NBLK_GATHER, 256>>>(X, outq, outidx);
    if (outs) finalize_kernel<<<1, 256>>>(outs);
}